// round 15
// baseline (speedup 1.0000x reference)
#include <cuda_runtime.h>
#include <cuda_fp16.h>
#include <cstdint>
#include <cstddef>

// Problem constants: B=4, I=64, O=64, K=3, H=W=512.
#define EPS_F 1e-8f

// ---------------------------------------------------------------------------
// Device scratch: x-Winograd-transformed modulated weights, packed so the TWO
// B fragments a warp needs per K-step are one LDG.128 per lane:
// uint4 index (per b, per xi): ((s*4 + npg)*32 + lane), s = kc*3 + ky,
// npg = o>>4. Within the uint4: words = { ni_even.hf0, ni_even.hf1,
// ni_odd.hf0, ni_odd.hf1 } where ni_even/odd = npg*2 + {0,1}, and lane l
// supplies kpair rows (l&3) / (l&3)+4 of the K16 step, o = ni*8 + (l>>2).
// xi=3 is stored NEGATED (A^T fold).
// ---------------------------------------------------------------------------
__device__ __align__(16) uint32_t g_wU[4 * 4 * 6144];                // 384 KB

__device__ __forceinline__ uint32_t smem_u32(const void* p) {
    uint32_t a;
    asm("{ .reg .u64 t; cvta.to.shared.u64 t, %1; cvt.u32.u64 %0, t; }"
        : "=r"(a) : "l"(p));
    return a;
}

// ---------------------------------------------------------------------------
// Kernel 1: modulate + demodulate + x-Winograd weight transform (U = G g).
// U0 = g0; U1 = (g0+g1+g2)/2; U2 = (g0-g1+g2)/2; U3 = -g2 (negated).
// ---------------------------------------------------------------------------
__global__ void modulate_kernel(const float* __restrict__ weight,   // (O=64, I=64, 3, 3)
                                const float* __restrict__ style) {  // (B=4, I=64)
    const int bo  = blockIdx.x;
    const int b   = bo >> 6;
    const int o   = bo & 63;
    const int tid = threadIdx.x;

    __shared__ float red[8];
    __shared__ float s_inv;

    float sum = 0.f;
    for (int idx = tid; idx < 576; idx += 256) {
        const int i = idx / 9;
        const float v = weight[o * 576 + idx] * style[b * 64 + i];
        sum += v * v;
    }
    #pragma unroll
    for (int off = 16; off; off >>= 1)
        sum += __shfl_down_sync(0xffffffffu, sum, off);
    if ((tid & 31) == 0) red[tid >> 5] = sum;
    __syncthreads();
    if (tid == 0) {
        float t = 0.f;
        #pragma unroll
        for (int k = 0; k < 8; k++) t += red[k];
        s_inv = rsqrtf(EPS_F + t);
    }
    __syncthreads();
    const float inv = s_inv;

    // 96 items: (cpair cp 0..31, ky 0..2)
    if (tid < 96) {
        const int cp = tid / 3;
        const int ky = tid - 3 * cp;
        const int c0 = 2 * cp;
        const float s0 = style[b * 64 + c0] * inv;
        const float s1 = style[b * 64 + c0 + 1] * inv;
        const float* w0 = weight + (o * 64 + c0) * 9 + ky * 3;
        const float g00 = w0[0] * s0, g01 = w0[1] * s0, g02 = w0[2] * s0;
        const float g10 = w0[9] * s1, g11 = w0[10] * s1, g12 = w0[11] * s1;

        float u0[4], u1[4];
        u0[0] = g00; u0[1] = 0.5f * (g00 + g01 + g02);
        u0[2] = 0.5f * (g00 - g01 + g02); u0[3] = -g02;    // xi=3 negated
        u1[0] = g10; u1[1] = 0.5f * (g10 + g11 + g12);
        u1[2] = 0.5f * (g10 - g11 + g12); u1[3] = -g12;    // xi=3 negated

        const int kc   = cp >> 3;               // channel 16-block (K16 step col)
        const int r    = cp & 7;                // kpair row within step
        const int t    = r & 3;
        const int hf   = r >> 2;
        const int s    = kc * 3 + ky;           // K-step index (kc-major)
        const int ln   = ((o & 7) << 2) | t;    // consuming lane
        const int npg  = o >> 4;                // ni-pair group
        const int wsel = ((o >> 3) & 1) * 2 + hf;
        #pragma unroll
        for (int xi = 0; xi < 4; xi++) {
            __half2 h = __floats2half2_rn(u0[xi], u1[xi]);
            g_wU[(size_t)(b * 4 + xi) * 6144
                 + (size_t)(((s * 4 + npg) * 32 + ln) * 4 + wsel)] =
                *reinterpret_cast<uint32_t*>(&h);
        }
    }
}

// ---------------------------------------------------------------------------
// Kernel 2: x-Winograd F(2,3) fp16 mma.sync conv, direct from NCHW fp32.
// 128 threads = 4 warps, each m32 x n32. CTA tile widened to 8 rows x 32 px
// (2 x-subtiles of M64 processed sequentially per warp) so the V-build's
// NCHW loads have 4 lanes per channel row -> ~2.7x fewer L1 wavefronts.
//
// Per xi per subtile: GEMM M64 x N64 x K192 (12 K-steps, kc-major).
// A^T fold: xi=0 -> Y0 (px0), xi=3 (pre-negated) -> Y1 (px1),
//           xi=1 -> temp, +Y0 +Y1;  xi=2 -> temp, +Y0 -Y1.
// V smem: V[xi][r(10)][xt(16)][c(64)] fp16, xt stride 144 B,
//         row stride 2320 B, xi stride 23200 B (92.8 KB total, 2 CTAs/SM).
// Warp (wm = wid&1, wn = wid>>1): rows [4wm, 4wm+4) x o range [wn*32, +32).
// ---------------------------------------------------------------------------
static constexpr int V_XT_STRIDE  = 144;
static constexpr int V_ROW_STRIDE = 16 * V_XT_STRIDE + 16;   // 2320 B
static constexpr int V_XI_STRIDE  = 10 * V_ROW_STRIDE;       // 23200 B
static constexpr int CONV_SMEM    = 4 * V_XI_STRIDE;         // 92800 B

#define LDSM4(dst, addr) \
    asm volatile("ldmatrix.sync.aligned.m8n8.x4.shared.b16 {%0,%1,%2,%3}, [%4];" \
        : "=r"((dst)[0]), "=r"((dst)[1]), "=r"((dst)[2]), "=r"((dst)[3]) \
        : "r"(addr))

// One xi-GEMM, m32n32: 12 K-steps (kc-major), A (2 m-tiles) from smem via
// ldmatrix, B via one LDG.128 per ni-pair; both double-buffered 1 step ahead.
__device__ __forceinline__ void gemm_xi(float (&acc)[2][4][4],
                                        uint32_t a0, uint32_t a1,
                                        const uint4* __restrict__ Ub) {
    uint32_t af[2][2][4];
    uint4    bv[2][2];
    LDSM4(af[0][0], a0);
    LDSM4(af[0][1], a1);
    bv[0][0] = __ldg(Ub);
    bv[0][1] = __ldg(Ub + 32);

    #pragma unroll
    for (int s = 0; s < 12; s++) {
        const int cur = s & 1, nxt = cur ^ 1;
        if (s < 11) {
            const int s1 = s + 1;
            const uint32_t off = (uint32_t)((s1 % 3) * V_ROW_STRIDE + (s1 / 3) * 32);
            LDSM4(af[nxt][0], a0 + off);
            LDSM4(af[nxt][1], a1 + off);
            bv[nxt][0] = __ldg(Ub + s1 * 128);
            bv[nxt][1] = __ldg(Ub + s1 * 128 + 32);
        }
        #pragma unroll
        for (int np = 0; np < 2; np++) {
            const uint4 q = bv[cur][np];
            #pragma unroll
            for (int mi = 0; mi < 2; mi++) {
                asm volatile(
                    "mma.sync.aligned.m16n8k16.row.col.f32.f16.f16.f32 "
                    "{%0,%1,%2,%3}, {%4,%5,%6,%7}, {%8,%9}, {%0,%1,%2,%3};"
                    : "+f"(acc[mi][np*2+0][0]), "+f"(acc[mi][np*2+0][1]),
                      "+f"(acc[mi][np*2+0][2]), "+f"(acc[mi][np*2+0][3])
                    : "r"(af[cur][mi][0]), "r"(af[cur][mi][1]),
                      "r"(af[cur][mi][2]), "r"(af[cur][mi][3]),
                      "r"(q.x), "r"(q.y));
                asm volatile(
                    "mma.sync.aligned.m16n8k16.row.col.f32.f16.f16.f32 "
                    "{%0,%1,%2,%3}, {%4,%5,%6,%7}, {%8,%9}, {%0,%1,%2,%3};"
                    : "+f"(acc[mi][np*2+1][0]), "+f"(acc[mi][np*2+1][1]),
                      "+f"(acc[mi][np*2+1][2]), "+f"(acc[mi][np*2+1][3])
                    : "r"(af[cur][mi][0]), "r"(af[cur][mi][1]),
                      "r"(af[cur][mi][2]), "r"(af[cur][mi][3]),
                      "r"(q.z), "r"(q.w));
            }
        }
    }
}

__global__ __launch_bounds__(128, 3)
void conv_kernel(const float* __restrict__ input,   // (4, 64, 512, 512) fp32 NCHW
                 float* __restrict__ out) {         // (4, 64, 512, 512)
    extern __shared__ __align__(16) char dsm[];

    const int tid  = threadIdx.x;
    const int lane = tid & 31;
    const int wid  = tid >> 5;
    const int b    = blockIdx.z;
    const int y0   = blockIdx.y << 3;
    const int x0   = blockIdx.x << 5;      // 32-px wide tile

    const uint32_t vsm0 = smem_u32(dsm);

    // ---- build V from NCHW fp32 ----
    // item = (r 0..9, cpair 0..31, xh 0..3): 1280 items = 128 thr x 10.
    // Warp-instr lanes = (8 cpairs x 4 xh) -> only 8 channel rows per load.
    {
        const float* in_b = input + (size_t)b * (64 * 512 * 512);
        #pragma unroll
        for (int it = 0; it < 10; it++) {
            const int idx = it * 128 + tid;
            const int xh  = idx & 3;
            const int cp  = (idx >> 2) & 31;
            const int r   = idx >> 7;
            const int gy  = y0 - 1 + r;
            const int gxb = x0 + 8 * xh - 4;
            const bool rowok = ((unsigned)gy < 512u);
            const float* p0 = in_b + ((size_t)(2 * cp) << 18) + ((size_t)gy << 9);
            const float* p1 = p0 + ((size_t)1 << 18);
            float f0[16], f1[16];
            #pragma unroll
            for (int q = 0; q < 4; q++) {
                const int gx = gxb + 4 * q;
                float4 v0 = make_float4(0.f, 0.f, 0.f, 0.f);
                float4 v1 = make_float4(0.f, 0.f, 0.f, 0.f);
                if (rowok && (unsigned)gx < 512u) {
                    v0 = *reinterpret_cast<const float4*>(p0 + gx);
                    v1 = *reinterpret_cast<const float4*>(p1 + gx);
                }
                f0[4*q] = v0.x; f0[4*q+1] = v0.y; f0[4*q+2] = v0.z; f0[4*q+3] = v0.w;
                f1[4*q] = v1.x; f1[4*q+1] = v1.y; f1[4*q+2] = v1.z; f1[4*q+3] = v1.w;
            }
            const uint32_t vbase = vsm0 + (uint32_t)(r * V_ROW_STRIDE + cp * 4);
            #pragma unroll
            for (int xq = 0; xq < 4; xq++) {
                const int i0 = 2 * xq + 3;             // d(-1) of window
                const int xt = 4 * xh + xq;            // x-tile 0..15
                const float a0 = f0[i0], a1 = f0[i0+1], a2 = f0[i0+2], a3 = f0[i0+3];
                const float c0 = f1[i0], c1 = f1[i0+1], c2 = f1[i0+2], c3 = f1[i0+3];
                __half2 h0 = __floats2half2_rn(a0 - a2, c0 - c2);
                __half2 h1 = __floats2half2_rn(a1 + a2, c1 + c2);
                __half2 h2 = __floats2half2_rn(a2 - a1, c2 - c1);
                __half2 h3 = __floats2half2_rn(a1 - a3, c1 - c3);
                const uint32_t va = vbase + (uint32_t)(xt * V_XT_STRIDE);
                asm volatile("st.shared.u32 [%0], %1;"
                             :: "r"(va),                 "r"(*(uint32_t*)&h0));
                asm volatile("st.shared.u32 [%0], %1;"
                             :: "r"(va + V_XI_STRIDE),   "r"(*(uint32_t*)&h1));
                asm volatile("st.shared.u32 [%0], %1;"
                             :: "r"(va + 2*V_XI_STRIDE), "r"(*(uint32_t*)&h2));
                asm volatile("st.shared.u32 [%0], %1;"
                             :: "r"(va + 3*V_XI_STRIDE), "r"(*(uint32_t*)&h3));
            }
        }
    }
    __syncthreads();      // the ONLY barrier

    const int wm = wid & 1;    // m: rows [4wm, 4wm+4)
    const int wn = wid >> 1;   // n: o range [wn*32, wn*32+32)

    // Common part of the ldmatrix A lane address (row/xt/k-half within tile).
    const uint32_t aCom = vsm0
        + (uint32_t)(((lane & 7) * V_XT_STRIDE) + (lane >> 4) * 16)
        + (uint32_t)((4 * wm + ((lane & 15) >> 3)) * V_ROW_STRIDE);

    // U fragment base for this warp (uint4 units; 1536 per xi)
    const uint4* Ub = reinterpret_cast<const uint4*>(g_wU)
                      + (size_t)(b * 4) * 1536 + (size_t)(wn * 2) * 32 + lane;

    #pragma unroll 1
    for (int xs = 0; xs < 2; xs++) {       // two 16-px x-subtiles
        const uint32_t a0 = aCom + (uint32_t)(xs * 8 * V_XT_STRIDE);
        const uint32_t a1 = a0 + (uint32_t)(2 * V_ROW_STRIDE);

        float Y0[2][4][4], Y1[2][4][4];
        #pragma unroll
        for (int mi = 0; mi < 2; mi++)
            #pragma unroll
            for (int ni = 0; ni < 4; ni++)
                #pragma unroll
                for (int j = 0; j < 4; j++) { Y0[mi][ni][j] = 0.f; Y1[mi][ni][j] = 0.f; }

        // xi = 0: directly into Y0 (px0 += M0)
        gemm_xi(Y0, a0, a1, Ub);
        // xi = 3 (pre-negated): directly into Y1 (px1 -= M3)
        gemm_xi(Y1, a0 + 3u * V_XI_STRIDE, a1 + 3u * V_XI_STRIDE, Ub + 3 * 1536);

        // xi = 1: temp, px0 += M1, px1 += M1
        {
            float m[2][4][4];
            #pragma unroll
            for (int mi = 0; mi < 2; mi++)
                #pragma unroll
                for (int ni = 0; ni < 4; ni++)
                    #pragma unroll
                    for (int j = 0; j < 4; j++) m[mi][ni][j] = 0.f;
            gemm_xi(m, a0 + 1u * V_XI_STRIDE, a1 + 1u * V_XI_STRIDE, Ub + 1 * 1536);
            #pragma unroll
            for (int mi = 0; mi < 2; mi++)
                #pragma unroll
                for (int ni = 0; ni < 4; ni++)
                    #pragma unroll
                    for (int j = 0; j < 4; j++) {
                        Y0[mi][ni][j] += m[mi][ni][j];
                        Y1[mi][ni][j] += m[mi][ni][j];
                    }
        }
        // xi = 2: temp, px0 += M2, px1 -= M2
        {
            float m[2][4][4];
            #pragma unroll
            for (int mi = 0; mi < 2; mi++)
                #pragma unroll
                for (int ni = 0; ni < 4; ni++)
                    #pragma unroll
                    for (int j = 0; j < 4; j++) m[mi][ni][j] = 0.f;
            gemm_xi(m, a0 + 2u * V_XI_STRIDE, a1 + 2u * V_XI_STRIDE, Ub + 2 * 1536);
            #pragma unroll
            for (int mi = 0; mi < 2; mi++)
                #pragma unroll
                for (int ni = 0; ni < 4; ni++)
                    #pragma unroll
                    for (int j = 0; j < 4; j++) {
                        Y0[mi][ni][j] += m[mi][ni][j];
                        Y1[mi][ni][j] -= m[mi][ni][j];
                    }
        }

        // ---- epilogue: STG.64 of adjacent output-px pairs (coalesced) ----
        const int xg = x0 + 16 * xs + 2 * (lane >> 2);
        #pragma unroll
        for (int mi = 0; mi < 2; mi++)
            #pragma unroll
            for (int yr = 0; yr < 2; yr++) {
                const int y = y0 + 4 * wm + 2 * mi + yr;
                #pragma unroll
                for (int ni = 0; ni < 4; ni++)
                    #pragma unroll
                    for (int j = 0; j < 2; j++) {
                        const int o = wn * 32 + ni * 8 + 2 * (lane & 3) + j;
                        float2 v = make_float2(Y0[mi][ni][yr * 2 + j],
                                               Y1[mi][ni][yr * 2 + j]);
                        *reinterpret_cast<float2*>(
                            out + ((size_t)(b * 64 + o) << 18)
                                + ((size_t)y << 9) + xg) = v;
                    }
            }
    }
}

// ---------------------------------------------------------------------------
// Harness entry point.
//   d_in[0] = input  (4, 64, 512, 512) float
//   d_in[1] = style  (4, 64)           float
//   d_in[2] = weight (64, 64, 3, 3)    float
//   d_out   = (4, 64, 512, 512) float
// ---------------------------------------------------------------------------
extern "C" void kernel_launch(void* const* d_in, const int* in_sizes, int n_in,
                              void* d_out, int out_size) {
    const float* input  = (const float*)d_in[0];
    const float* style  = (const float*)d_in[1];
    const float* weight = (const float*)d_in[2];
    float* out = (float*)d_out;

    cudaFuncSetAttribute(conv_kernel, cudaFuncAttributeMaxDynamicSharedMemorySize,
                         CONV_SMEM);

    modulate_kernel<<<256, 256>>>(weight, style);
    conv_kernel<<<dim3(16, 64, 4), 128, CONV_SMEM>>>(input, out);
}

// round 16
// speedup vs baseline: 1.0052x; 1.0052x over previous
#include <cuda_runtime.h>
#include <cuda_fp16.h>
#include <cstdint>
#include <cstddef>

// Problem constants: B=4, I=64, O=64, K=3, H=W=512.
#define EPS_F 1e-8f

// ---------------------------------------------------------------------------
// Device scratch: x-Winograd-transformed modulated weights, packed so the TWO
// B fragments a warp needs per K-step are one LDG.128 per lane:
// uint4 index (per b, per xi): ((s*4 + npg)*32 + lane), s = kc*3 + ky,
// npg = o>>4. Within the uint4: words = { ni_even.hf0, ni_even.hf1,
// ni_odd.hf0, ni_odd.hf1 } where ni_even/odd = npg*2 + {0,1}, and lane l
// supplies kpair rows (l&3) / (l&3)+4 of the K16 step, o = ni*8 + (l>>2).
// xi=3 is stored NEGATED (A^T fold).
// ---------------------------------------------------------------------------
__device__ __align__(16) uint32_t g_wU[4 * 4 * 6144];                // 384 KB

__device__ __forceinline__ uint32_t smem_u32(const void* p) {
    uint32_t a;
    asm("{ .reg .u64 t; cvta.to.shared.u64 t, %1; cvt.u32.u64 %0, t; }"
        : "=r"(a) : "l"(p));
    return a;
}

// ---------------------------------------------------------------------------
// Kernel 1: modulate + demodulate + x-Winograd weight transform (U = G g).
// U0 = g0; U1 = (g0+g1+g2)/2; U2 = (g0-g1+g2)/2; U3 = -g2 (negated).
// ---------------------------------------------------------------------------
__global__ void modulate_kernel(const float* __restrict__ weight,   // (O=64, I=64, 3, 3)
                                const float* __restrict__ style) {  // (B=4, I=64)
    const int bo  = blockIdx.x;
    const int b   = bo >> 6;
    const int o   = bo & 63;
    const int tid = threadIdx.x;

    __shared__ float red[8];
    __shared__ float s_inv;

    float sum = 0.f;
    for (int idx = tid; idx < 576; idx += 256) {
        const int i = idx / 9;
        const float v = weight[o * 576 + idx] * style[b * 64 + i];
        sum += v * v;
    }
    #pragma unroll
    for (int off = 16; off; off >>= 1)
        sum += __shfl_down_sync(0xffffffffu, sum, off);
    if ((tid & 31) == 0) red[tid >> 5] = sum;
    __syncthreads();
    if (tid == 0) {
        float t = 0.f;
        #pragma unroll
        for (int k = 0; k < 8; k++) t += red[k];
        s_inv = rsqrtf(EPS_F + t);
    }
    __syncthreads();
    const float inv = s_inv;

    // 96 items: (cpair cp 0..31, ky 0..2)
    if (tid < 96) {
        const int cp = tid / 3;
        const int ky = tid - 3 * cp;
        const int c0 = 2 * cp;
        const float s0 = style[b * 64 + c0] * inv;
        const float s1 = style[b * 64 + c0 + 1] * inv;
        const float* w0 = weight + (o * 64 + c0) * 9 + ky * 3;
        const float g00 = w0[0] * s0, g01 = w0[1] * s0, g02 = w0[2] * s0;
        const float g10 = w0[9] * s1, g11 = w0[10] * s1, g12 = w0[11] * s1;

        float u0[4], u1[4];
        u0[0] = g00; u0[1] = 0.5f * (g00 + g01 + g02);
        u0[2] = 0.5f * (g00 - g01 + g02); u0[3] = -g02;    // xi=3 negated
        u1[0] = g10; u1[1] = 0.5f * (g10 + g11 + g12);
        u1[2] = 0.5f * (g10 - g11 + g12); u1[3] = -g12;    // xi=3 negated

        const int kc   = cp >> 3;               // channel 16-block (K16 step col)
        const int r    = cp & 7;                // kpair row within step
        const int t    = r & 3;
        const int hf   = r >> 2;
        const int s    = kc * 3 + ky;           // K-step index (kc-major)
        const int ln   = ((o & 7) << 2) | t;    // consuming lane
        const int npg  = o >> 4;                // ni-pair group
        const int wsel = ((o >> 3) & 1) * 2 + hf;
        #pragma unroll
        for (int xi = 0; xi < 4; xi++) {
            __half2 h = __floats2half2_rn(u0[xi], u1[xi]);
            g_wU[(size_t)(b * 4 + xi) * 6144
                 + (size_t)(((s * 4 + npg) * 32 + ln) * 4 + wsel)] =
                *reinterpret_cast<uint32_t*>(&h);
        }
    }
}

// ---------------------------------------------------------------------------
// Kernel 2: x-Winograd F(2,3) fp16 mma.sync conv, direct from NCHW fp32.
// 128 threads = 4 warps, each m32 x n32. CTA tile widened to 8 rows x 32 px
// (2 x-subtiles of M64 processed sequentially per warp) so the V-build's
// NCHW loads have 4 lanes per channel row -> ~2.7x fewer L1 wavefronts.
//
// Per xi per subtile: GEMM M64 x N64 x K192 (12 K-steps, kc-major).
// A^T fold: xi=0 -> Y0 (px0), xi=3 (pre-negated) -> Y1 (px1),
//           xi=1 -> temp, +Y0 +Y1;  xi=2 -> temp, +Y0 -Y1.
// V smem: V[xi][r(10)][xt(16)][c(64)] fp16, xt stride 144 B,
//         row stride 2320 B, xi stride 23200 B (92.8 KB total, 2 CTAs/SM).
// Warp (wm = wid&1, wn = wid>>1): rows [4wm, 4wm+4) x o range [wn*32, +32).
// ---------------------------------------------------------------------------
static constexpr int V_XT_STRIDE  = 144;
static constexpr int V_ROW_STRIDE = 16 * V_XT_STRIDE + 16;   // 2320 B
static constexpr int V_XI_STRIDE  = 10 * V_ROW_STRIDE;       // 23200 B
static constexpr int CONV_SMEM    = 4 * V_XI_STRIDE;         // 92800 B

#define LDSM4(dst, addr) \
    asm volatile("ldmatrix.sync.aligned.m8n8.x4.shared.b16 {%0,%1,%2,%3}, [%4];" \
        : "=r"((dst)[0]), "=r"((dst)[1]), "=r"((dst)[2]), "=r"((dst)[3]) \
        : "r"(addr))

// One xi-GEMM, m32n32: 12 K-steps (kc-major), A (2 m-tiles) from smem via
// ldmatrix, B via one LDG.128 per ni-pair; both double-buffered 1 step ahead.
__device__ __forceinline__ void gemm_xi(float (&acc)[2][4][4],
                                        uint32_t a0, uint32_t a1,
                                        const uint4* __restrict__ Ub) {
    uint32_t af[2][2][4];
    uint4    bv[2][2];
    LDSM4(af[0][0], a0);
    LDSM4(af[0][1], a1);
    bv[0][0] = __ldg(Ub);
    bv[0][1] = __ldg(Ub + 32);

    #pragma unroll
    for (int s = 0; s < 12; s++) {
        const int cur = s & 1, nxt = cur ^ 1;
        if (s < 11) {
            const int s1 = s + 1;
            const uint32_t off = (uint32_t)((s1 % 3) * V_ROW_STRIDE + (s1 / 3) * 32);
            LDSM4(af[nxt][0], a0 + off);
            LDSM4(af[nxt][1], a1 + off);
            bv[nxt][0] = __ldg(Ub + s1 * 128);
            bv[nxt][1] = __ldg(Ub + s1 * 128 + 32);
        }
        #pragma unroll
        for (int np = 0; np < 2; np++) {
            const uint4 q = bv[cur][np];
            #pragma unroll
            for (int mi = 0; mi < 2; mi++) {
                asm volatile(
                    "mma.sync.aligned.m16n8k16.row.col.f32.f16.f16.f32 "
                    "{%0,%1,%2,%3}, {%4,%5,%6,%7}, {%8,%9}, {%0,%1,%2,%3};"
                    : "+f"(acc[mi][np*2+0][0]), "+f"(acc[mi][np*2+0][1]),
                      "+f"(acc[mi][np*2+0][2]), "+f"(acc[mi][np*2+0][3])
                    : "r"(af[cur][mi][0]), "r"(af[cur][mi][1]),
                      "r"(af[cur][mi][2]), "r"(af[cur][mi][3]),
                      "r"(q.x), "r"(q.y));
                asm volatile(
                    "mma.sync.aligned.m16n8k16.row.col.f32.f16.f16.f32 "
                    "{%0,%1,%2,%3}, {%4,%5,%6,%7}, {%8,%9}, {%0,%1,%2,%3};"
                    : "+f"(acc[mi][np*2+1][0]), "+f"(acc[mi][np*2+1][1]),
                      "+f"(acc[mi][np*2+1][2]), "+f"(acc[mi][np*2+1][3])
                    : "r"(af[cur][mi][0]), "r"(af[cur][mi][1]),
                      "r"(af[cur][mi][2]), "r"(af[cur][mi][3]),
                      "r"(q.z), "r"(q.w));
            }
        }
    }
}

__global__ __launch_bounds__(128, 3)
void conv_kernel(const float* __restrict__ input,   // (4, 64, 512, 512) fp32 NCHW
                 float* __restrict__ out) {         // (4, 64, 512, 512)
    extern __shared__ __align__(16) char dsm[];

    const int tid  = threadIdx.x;
    const int lane = tid & 31;
    const int wid  = tid >> 5;
    const int b    = blockIdx.z;
    const int y0   = blockIdx.y << 3;
    const int x0   = blockIdx.x << 5;      // 32-px wide tile

    const uint32_t vsm0 = smem_u32(dsm);

    // ---- build V from NCHW fp32 ----
    // item = (r 0..9, cpair 0..31, xh 0..3): 1280 items = 128 thr x 10.
    // Warp-instr lanes = (8 cpairs x 4 xh) -> only 8 channel rows per load.
    {
        const float* in_b = input + (size_t)b * (64 * 512 * 512);
        #pragma unroll
        for (int it = 0; it < 10; it++) {
            const int idx = it * 128 + tid;
            const int xh  = idx & 3;
            const int cp  = (idx >> 2) & 31;
            const int r   = idx >> 7;
            const int gy  = y0 - 1 + r;
            const int gxb = x0 + 8 * xh - 4;
            const bool rowok = ((unsigned)gy < 512u);
            const float* p0 = in_b + ((size_t)(2 * cp) << 18) + ((size_t)gy << 9);
            const float* p1 = p0 + ((size_t)1 << 18);
            float f0[16], f1[16];
            #pragma unroll
            for (int q = 0; q < 4; q++) {
                const int gx = gxb + 4 * q;
                float4 v0 = make_float4(0.f, 0.f, 0.f, 0.f);
                float4 v1 = make_float4(0.f, 0.f, 0.f, 0.f);
                if (rowok && (unsigned)gx < 512u) {
                    v0 = *reinterpret_cast<const float4*>(p0 + gx);
                    v1 = *reinterpret_cast<const float4*>(p1 + gx);
                }
                f0[4*q] = v0.x; f0[4*q+1] = v0.y; f0[4*q+2] = v0.z; f0[4*q+3] = v0.w;
                f1[4*q] = v1.x; f1[4*q+1] = v1.y; f1[4*q+2] = v1.z; f1[4*q+3] = v1.w;
            }
            const uint32_t vbase = vsm0 + (uint32_t)(r * V_ROW_STRIDE + cp * 4);
            #pragma unroll
            for (int xq = 0; xq < 4; xq++) {
                const int i0 = 2 * xq + 3;             // d(-1) of window
                const int xt = 4 * xh + xq;            // x-tile 0..15
                const float a0 = f0[i0], a1 = f0[i0+1], a2 = f0[i0+2], a3 = f0[i0+3];
                const float c0 = f1[i0], c1 = f1[i0+1], c2 = f1[i0+2], c3 = f1[i0+3];
                __half2 h0 = __floats2half2_rn(a0 - a2, c0 - c2);
                __half2 h1 = __floats2half2_rn(a1 + a2, c1 + c2);
                __half2 h2 = __floats2half2_rn(a2 - a1, c2 - c1);
                __half2 h3 = __floats2half2_rn(a1 - a3, c1 - c3);
                const uint32_t va = vbase + (uint32_t)(xt * V_XT_STRIDE);
                asm volatile("st.shared.u32 [%0], %1;"
                             :: "r"(va),                 "r"(*(uint32_t*)&h0));
                asm volatile("st.shared.u32 [%0], %1;"
                             :: "r"(va + V_XI_STRIDE),   "r"(*(uint32_t*)&h1));
                asm volatile("st.shared.u32 [%0], %1;"
                             :: "r"(va + 2*V_XI_STRIDE), "r"(*(uint32_t*)&h2));
                asm volatile("st.shared.u32 [%0], %1;"
                             :: "r"(va + 3*V_XI_STRIDE), "r"(*(uint32_t*)&h3));
            }
        }
    }
    __syncthreads();      // the ONLY barrier

    const int wm = wid & 1;    // m: rows [4wm, 4wm+4)
    const int wn = wid >> 1;   // n: o range [wn*32, wn*32+32)

    // Common part of the ldmatrix A lane address (row/xt/k-half within tile).
    const uint32_t aCom = vsm0
        + (uint32_t)(((lane & 7) * V_XT_STRIDE) + (lane >> 4) * 16)
        + (uint32_t)((4 * wm + ((lane & 15) >> 3)) * V_ROW_STRIDE);

    // U fragment base for this warp (uint4 units; 1536 per xi)
    const uint4* Ub = reinterpret_cast<const uint4*>(g_wU)
                      + (size_t)(b * 4) * 1536 + (size_t)(wn * 2) * 32 + lane;

    #pragma unroll 1
    for (int xs = 0; xs < 2; xs++) {       // two 16-px x-subtiles
        const uint32_t a0 = aCom + (uint32_t)(xs * 8 * V_XT_STRIDE);
        const uint32_t a1 = a0 + (uint32_t)(2 * V_ROW_STRIDE);

        float Y0[2][4][4], Y1[2][4][4];
        #pragma unroll
        for (int mi = 0; mi < 2; mi++)
            #pragma unroll
            for (int ni = 0; ni < 4; ni++)
                #pragma unroll
                for (int j = 0; j < 4; j++) { Y0[mi][ni][j] = 0.f; Y1[mi][ni][j] = 0.f; }

        // xi = 0: directly into Y0 (px0 += M0)
        gemm_xi(Y0, a0, a1, Ub);
        // xi = 3 (pre-negated): directly into Y1 (px1 -= M3)
        gemm_xi(Y1, a0 + 3u * V_XI_STRIDE, a1 + 3u * V_XI_STRIDE, Ub + 3 * 1536);

        // xi = 1: temp, px0 += M1, px1 += M1
        {
            float m[2][4][4];
            #pragma unroll
            for (int mi = 0; mi < 2; mi++)
                #pragma unroll
                for (int ni = 0; ni < 4; ni++)
                    #pragma unroll
                    for (int j = 0; j < 4; j++) m[mi][ni][j] = 0.f;
            gemm_xi(m, a0 + 1u * V_XI_STRIDE, a1 + 1u * V_XI_STRIDE, Ub + 1 * 1536);
            #pragma unroll
            for (int mi = 0; mi < 2; mi++)
                #pragma unroll
                for (int ni = 0; ni < 4; ni++)
                    #pragma unroll
                    for (int j = 0; j < 4; j++) {
                        Y0[mi][ni][j] += m[mi][ni][j];
                        Y1[mi][ni][j] += m[mi][ni][j];
                    }
        }
        // xi = 2: temp, px0 += M2, px1 -= M2
        {
            float m[2][4][4];
            #pragma unroll
            for (int mi = 0; mi < 2; mi++)
                #pragma unroll
                for (int ni = 0; ni < 4; ni++)
                    #pragma unroll
                    for (int j = 0; j < 4; j++) m[mi][ni][j] = 0.f;
            gemm_xi(m, a0 + 2u * V_XI_STRIDE, a1 + 2u * V_XI_STRIDE, Ub + 2 * 1536);
            #pragma unroll
            for (int mi = 0; mi < 2; mi++)
                #pragma unroll
                for (int ni = 0; ni < 4; ni++)
                    #pragma unroll
                    for (int j = 0; j < 4; j++) {
                        Y0[mi][ni][j] += m[mi][ni][j];
                        Y1[mi][ni][j] -= m[mi][ni][j];
                    }
        }

        // ---- epilogue: STG.64 of adjacent output-px pairs (coalesced) ----
        const int xg = x0 + 16 * xs + 2 * (lane >> 2);
        #pragma unroll
        for (int mi = 0; mi < 2; mi++)
            #pragma unroll
            for (int yr = 0; yr < 2; yr++) {
                const int y = y0 + 4 * wm + 2 * mi + yr;
                #pragma unroll
                for (int ni = 0; ni < 4; ni++)
                    #pragma unroll
                    for (int j = 0; j < 2; j++) {
                        const int o = wn * 32 + ni * 8 + 2 * (lane & 3) + j;
                        float2 v = make_float2(Y0[mi][ni][yr * 2 + j],
                                               Y1[mi][ni][yr * 2 + j]);
                        *reinterpret_cast<float2*>(
                            out + ((size_t)(b * 64 + o) << 18)
                                + ((size_t)y << 9) + xg) = v;
                    }
            }
    }
}

// ---------------------------------------------------------------------------
// Harness entry point.
//   d_in[0] = input  (4, 64, 512, 512) float
//   d_in[1] = style  (4, 64)           float
//   d_in[2] = weight (64, 64, 3, 3)    float
//   d_out   = (4, 64, 512, 512) float
// ---------------------------------------------------------------------------
extern "C" void kernel_launch(void* const* d_in, const int* in_sizes, int n_in,
                              void* d_out, int out_size) {
    const float* input  = (const float*)d_in[0];
    const float* style  = (const float*)d_in[1];
    const float* weight = (const float*)d_in[2];
    float* out = (float*)d_out;

    cudaFuncSetAttribute(conv_kernel, cudaFuncAttributeMaxDynamicSharedMemorySize,
                         CONV_SMEM);

    modulate_kernel<<<256, 256>>>(weight, style);
    conv_kernel<<<dim3(16, 64, 4), 128, CONV_SMEM>>>(input, out);
}

// round 17
// speedup vs baseline: 1.1513x; 1.1453x over previous
#include <cuda_runtime.h>
#include <cuda_fp16.h>
#include <cstdint>
#include <cstddef>

// Problem constants: B=4, I=64, O=64, K=3, H=W=512.
#define EPS_F 1e-8f

// ---------------------------------------------------------------------------
// Device scratch: x-Winograd-transformed modulated weights, packed so the TWO
// B fragments a warp needs per K-step are one LDG.128 per lane:
// uint4 index (per b, per xi): ((s*4 + npg)*32 + lane), s = kc*3 + ky,
// npg = o>>4. Within the uint4: words = { ni_even.hf0, ni_even.hf1,
// ni_odd.hf0, ni_odd.hf1 } where ni_even/odd = npg*2 + {0,1}, and lane l
// supplies kpair rows (l&3) / (l&3)+4 of the K16 step, o = ni*8 + (l>>2).
// xi=3 is stored NEGATED (A^T fold).
// ---------------------------------------------------------------------------
__device__ __align__(16) uint32_t g_wU[4 * 4 * 6144];                // 384 KB

__device__ __forceinline__ uint32_t smem_u32(const void* p) {
    uint32_t a;
    asm("{ .reg .u64 t; cvta.to.shared.u64 t, %1; cvt.u32.u64 %0, t; }"
        : "=r"(a) : "l"(p));
    return a;
}

// ---------------------------------------------------------------------------
// Kernel 1: modulate + demodulate + x-Winograd weight transform (U = G g).
// U0 = g0; U1 = (g0+g1+g2)/2; U2 = (g0-g1+g2)/2; U3 = -g2 (negated).
// ---------------------------------------------------------------------------
__global__ void modulate_kernel(const float* __restrict__ weight,   // (O=64, I=64, 3, 3)
                                const float* __restrict__ style) {  // (B=4, I=64)
    const int bo  = blockIdx.x;
    const int b   = bo >> 6;
    const int o   = bo & 63;
    const int tid = threadIdx.x;

    __shared__ float red[8];
    __shared__ float s_inv;

    float sum = 0.f;
    for (int idx = tid; idx < 576; idx += 256) {
        const int i = idx / 9;
        const float v = weight[o * 576 + idx] * style[b * 64 + i];
        sum += v * v;
    }
    #pragma unroll
    for (int off = 16; off; off >>= 1)
        sum += __shfl_down_sync(0xffffffffu, sum, off);
    if ((tid & 31) == 0) red[tid >> 5] = sum;
    __syncthreads();
    if (tid == 0) {
        float t = 0.f;
        #pragma unroll
        for (int k = 0; k < 8; k++) t += red[k];
        s_inv = rsqrtf(EPS_F + t);
    }
    __syncthreads();
    const float inv = s_inv;

    // 96 items: (cpair cp 0..31, ky 0..2)
    if (tid < 96) {
        const int cp = tid / 3;
        const int ky = tid - 3 * cp;
        const int c0 = 2 * cp;
        const float s0 = style[b * 64 + c0] * inv;
        const float s1 = style[b * 64 + c0 + 1] * inv;
        const float* w0 = weight + (o * 64 + c0) * 9 + ky * 3;
        const float g00 = w0[0] * s0, g01 = w0[1] * s0, g02 = w0[2] * s0;
        const float g10 = w0[9] * s1, g11 = w0[10] * s1, g12 = w0[11] * s1;

        float u0[4], u1[4];
        u0[0] = g00; u0[1] = 0.5f * (g00 + g01 + g02);
        u0[2] = 0.5f * (g00 - g01 + g02); u0[3] = -g02;    // xi=3 negated
        u1[0] = g10; u1[1] = 0.5f * (g10 + g11 + g12);
        u1[2] = 0.5f * (g10 - g11 + g12); u1[3] = -g12;    // xi=3 negated

        const int kc   = cp >> 3;               // channel 16-block (K16 step col)
        const int r    = cp & 7;                // kpair row within step
        const int t    = r & 3;
        const int hf   = r >> 2;
        const int s    = kc * 3 + ky;           // K-step index (kc-major)
        const int ln   = ((o & 7) << 2) | t;    // consuming lane
        const int npg  = o >> 4;                // ni-pair group
        const int wsel = ((o >> 3) & 1) * 2 + hf;
        #pragma unroll
        for (int xi = 0; xi < 4; xi++) {
            __half2 h = __floats2half2_rn(u0[xi], u1[xi]);
            g_wU[(size_t)(b * 4 + xi) * 6144
                 + (size_t)(((s * 4 + npg) * 32 + ln) * 4 + wsel)] =
                *reinterpret_cast<uint32_t*>(&h);
        }
    }
}

// ---------------------------------------------------------------------------
// Kernel 2: x-Winograd F(2,3) fp16 mma.sync conv, direct from NCHW fp32.
// R14 frame (16-px tile, 128 thr, 3 CTAs/SM) with a chunk-per-lane V build:
// lane = (cp-slot 0..4, chunk c 0..5); each warp-load touches only 5 channel
// rows x 96 B contiguous -> ~2.5x fewer L1 wavefronts in the prologue.
// Window px come from own chunk + __shfl_down(1) of the next chunk.
//
// Per xi: GEMM M64 x N64 x K192 (12 K-steps, kc-major), B via LDG.128 pairs.
// A^T fold: xi=0 -> Y0 (px0), xi=3 (pre-negated) -> Y1 (px1),
//           xi=1 -> temp, +Y0 +Y1;  xi=2 -> temp, +Y0 -Y1.
// V smem: V[xi][r(10)][xt(8)][c(64)] fp16, xt stride 144 B, row stride 1168 B.
// Warp (wm = wid&1, wn = wid>>1): rows [4wm, 4wm+4) x o range [wn*32, +32).
// ---------------------------------------------------------------------------
static constexpr int V_XT_STRIDE  = 144;
static constexpr int V_ROW_STRIDE = 8 * V_XT_STRIDE + 16;    // 1168 B
static constexpr int V_XI_STRIDE  = 10 * V_ROW_STRIDE;       // 11680 B
static constexpr int CONV_SMEM    = 4 * V_XI_STRIDE;         // 46720 B

#define LDSM4(dst, addr) \
    asm volatile("ldmatrix.sync.aligned.m8n8.x4.shared.b16 {%0,%1,%2,%3}, [%4];" \
        : "=r"((dst)[0]), "=r"((dst)[1]), "=r"((dst)[2]), "=r"((dst)[3]) \
        : "r"(addr))

// Winograd transform of one 4-px window (two channel planes) + 4 STS.
__device__ __forceinline__ void st_window(uint32_t va,
    float a0, float a1, float a2, float a3,
    float c0, float c1, float c2, float c3) {
    __half2 h0 = __floats2half2_rn(a0 - a2, c0 - c2);
    __half2 h1 = __floats2half2_rn(a1 + a2, c1 + c2);
    __half2 h2 = __floats2half2_rn(a2 - a1, c2 - c1);
    __half2 h3 = __floats2half2_rn(a1 - a3, c1 - c3);
    asm volatile("st.shared.u32 [%0], %1;" :: "r"(va),                 "r"(*(uint32_t*)&h0));
    asm volatile("st.shared.u32 [%0], %1;" :: "r"(va + V_XI_STRIDE),   "r"(*(uint32_t*)&h1));
    asm volatile("st.shared.u32 [%0], %1;" :: "r"(va + 2*V_XI_STRIDE), "r"(*(uint32_t*)&h2));
    asm volatile("st.shared.u32 [%0], %1;" :: "r"(va + 3*V_XI_STRIDE), "r"(*(uint32_t*)&h3));
}

// One xi-GEMM, m32n32: 12 K-steps (kc-major), A (2 m-tiles) from smem via
// ldmatrix, B via one LDG.128 per ni-pair; both double-buffered 1 step ahead.
__device__ __forceinline__ void gemm_xi(float (&acc)[2][4][4],
                                        uint32_t a0, uint32_t a1,
                                        const uint4* __restrict__ Ub) {
    uint32_t af[2][2][4];
    uint4    bv[2][2];
    LDSM4(af[0][0], a0);
    LDSM4(af[0][1], a1);
    bv[0][0] = __ldg(Ub);
    bv[0][1] = __ldg(Ub + 32);

    #pragma unroll
    for (int s = 0; s < 12; s++) {
        const int cur = s & 1, nxt = cur ^ 1;
        if (s < 11) {
            const int s1 = s + 1;
            const uint32_t off = (uint32_t)((s1 % 3) * V_ROW_STRIDE + (s1 / 3) * 32);
            LDSM4(af[nxt][0], a0 + off);
            LDSM4(af[nxt][1], a1 + off);
            bv[nxt][0] = __ldg(Ub + s1 * 128);
            bv[nxt][1] = __ldg(Ub + s1 * 128 + 32);
        }
        #pragma unroll
        for (int np = 0; np < 2; np++) {
            const uint4 q = bv[cur][np];
            #pragma unroll
            for (int mi = 0; mi < 2; mi++) {
                asm volatile(
                    "mma.sync.aligned.m16n8k16.row.col.f32.f16.f16.f32 "
                    "{%0,%1,%2,%3}, {%4,%5,%6,%7}, {%8,%9}, {%0,%1,%2,%3};"
                    : "+f"(acc[mi][np*2+0][0]), "+f"(acc[mi][np*2+0][1]),
                      "+f"(acc[mi][np*2+0][2]), "+f"(acc[mi][np*2+0][3])
                    : "r"(af[cur][mi][0]), "r"(af[cur][mi][1]),
                      "r"(af[cur][mi][2]), "r"(af[cur][mi][3]),
                      "r"(q.x), "r"(q.y));
                asm volatile(
                    "mma.sync.aligned.m16n8k16.row.col.f32.f16.f16.f32 "
                    "{%0,%1,%2,%3}, {%4,%5,%6,%7}, {%8,%9}, {%0,%1,%2,%3};"
                    : "+f"(acc[mi][np*2+1][0]), "+f"(acc[mi][np*2+1][1]),
                      "+f"(acc[mi][np*2+1][2]), "+f"(acc[mi][np*2+1][3])
                    : "r"(af[cur][mi][0]), "r"(af[cur][mi][1]),
                      "r"(af[cur][mi][2]), "r"(af[cur][mi][3]),
                      "r"(q.z), "r"(q.w));
            }
        }
    }
}

__global__ __launch_bounds__(128, 3)
void conv_kernel(const float* __restrict__ input,   // (4, 64, 512, 512) fp32 NCHW
                 float* __restrict__ out) {         // (4, 64, 512, 512)
    extern __shared__ __align__(16) char dsm[];

    const int tid  = threadIdx.x;
    const int lane = tid & 31;
    const int wid  = tid >> 5;
    const int b    = blockIdx.z;
    const int y0   = blockIdx.y << 3;
    const int x0   = blockIdx.x << 4;

    const uint32_t vsm0 = smem_u32(dsm);

    // ---- build V from NCHW fp32 (chunk-per-lane + shuffles) ----
    // lane = (slot = lane/6 in 0..4, chunk c = lane%6); lanes 30,31 idle.
    // cp-row index g = (it*4 + wid)*5 + slot, it in 0..15 (4 passes x 4).
    // Chunk c = float4 at halo px [4c, 4c+4) (halo = px [x0-4, x0+20)).
    // Window xt starts at halo px s = 2*xt+3 (odd):
    //   window A (off 1, xt=2c-1, c in 1..4): d = f.yzw, next.x
    //   window B (off 3, xt=2c,   c in 0..3): d = f.w, next.xyz
    {
        const float* in_b = input + (size_t)b * (64 * 512 * 512);
        const int  slot   = lane / 6;
        const int  c      = lane - 6 * slot;
        const bool active = lane < 30;
        const int  gx0    = x0 - 4 + 4 * c;

        #pragma unroll 1
        for (int pass = 0; pass < 4; pass++) {
            float4 F0[4], F1[4];
            int    G[4];
            // load phase: 8 independent LDG.128 in flight
            #pragma unroll
            for (int k = 0; k < 4; k++) {
                const int it = pass * 4 + k;
                const int g  = (it * 4 + wid) * 5 + slot;
                G[k] = g;
                const int gy = y0 - 1 + (g >> 5);
                const int cp = g & 31;
                const bool ok = active && (unsigned)gy < 512u
                                       && (unsigned)gx0 < 512u && g < 320;
                F0[k] = make_float4(0.f, 0.f, 0.f, 0.f);
                F1[k] = make_float4(0.f, 0.f, 0.f, 0.f);
                if (ok) {
                    const float* p0 = in_b + ((size_t)(2 * cp) << 18)
                                           + ((size_t)gy << 9) + gx0;
                    F0[k] = *reinterpret_cast<const float4*>(p0);
                    F1[k] = *reinterpret_cast<const float4*>(p0 + (1 << 18));
                }
            }
            // transform + store phase
            #pragma unroll
            for (int k = 0; k < 4; k++) {
                const float n00 = __shfl_down_sync(0xffffffffu, F0[k].x, 1);
                const float n01 = __shfl_down_sync(0xffffffffu, F0[k].y, 1);
                const float n02 = __shfl_down_sync(0xffffffffu, F0[k].z, 1);
                const float n10 = __shfl_down_sync(0xffffffffu, F1[k].x, 1);
                const float n11 = __shfl_down_sync(0xffffffffu, F1[k].y, 1);
                const float n12 = __shfl_down_sync(0xffffffffu, F1[k].z, 1);
                const int g  = G[k];
                const int cp = g & 31;
                const uint32_t vbase = vsm0
                    + (uint32_t)((g >> 5) * V_ROW_STRIDE + cp * 4);
                if (active && g < 320) {
                    if (c <= 3)                 // window B: xt = 2c
                        st_window(vbase + (uint32_t)(2 * c) * V_XT_STRIDE,
                                  F0[k].w, n00, n01, n02,
                                  F1[k].w, n10, n11, n12);
                    if (c >= 1 && c <= 4)       // window A: xt = 2c-1
                        st_window(vbase + (uint32_t)(2 * c - 1) * V_XT_STRIDE,
                                  F0[k].y, F0[k].z, F0[k].w, n00,
                                  F1[k].y, F1[k].z, F1[k].w, n10);
                }
            }
        }
    }
    __syncthreads();      // the ONLY barrier

    const int wm = wid & 1;    // m: rows [4wm, 4wm+4)
    const int wn = wid >> 1;   // n: o range [wn*32, wn*32+32)

    // ldmatrix A lane bases for the 2 m16-tiles of this warp.
    const uint32_t aCom = vsm0
        + (uint32_t)(((lane & 7) * V_XT_STRIDE) + (lane >> 4) * 16);
    const uint32_t a0 = aCom
        + (uint32_t)((4 * wm + ((lane & 15) >> 3)) * V_ROW_STRIDE);
    const uint32_t a1 = a0 + (uint32_t)(2 * V_ROW_STRIDE);

    // U fragment base for this warp (uint4 units; 1536 per xi)
    const uint4* Ub = reinterpret_cast<const uint4*>(g_wU)
                      + (size_t)(b * 4) * 1536 + (size_t)(wn * 2) * 32 + lane;

    float Y0[2][4][4], Y1[2][4][4];
    #pragma unroll
    for (int mi = 0; mi < 2; mi++)
        #pragma unroll
        for (int ni = 0; ni < 4; ni++)
            #pragma unroll
            for (int j = 0; j < 4; j++) { Y0[mi][ni][j] = 0.f; Y1[mi][ni][j] = 0.f; }

    // xi = 0: directly into Y0 (px0 += M0)
    gemm_xi(Y0, a0, a1, Ub);
    // xi = 3 (pre-negated): directly into Y1 (px1 -= M3)
    gemm_xi(Y1, a0 + 3u * V_XI_STRIDE, a1 + 3u * V_XI_STRIDE, Ub + 3 * 1536);

    // xi = 1: temp, px0 += M1, px1 += M1
    {
        float m[2][4][4];
        #pragma unroll
        for (int mi = 0; mi < 2; mi++)
            #pragma unroll
            for (int ni = 0; ni < 4; ni++)
                #pragma unroll
                for (int j = 0; j < 4; j++) m[mi][ni][j] = 0.f;
        gemm_xi(m, a0 + 1u * V_XI_STRIDE, a1 + 1u * V_XI_STRIDE, Ub + 1 * 1536);
        #pragma unroll
        for (int mi = 0; mi < 2; mi++)
            #pragma unroll
            for (int ni = 0; ni < 4; ni++)
                #pragma unroll
                for (int j = 0; j < 4; j++) {
                    Y0[mi][ni][j] += m[mi][ni][j];
                    Y1[mi][ni][j] += m[mi][ni][j];
                }
    }
    // xi = 2: temp, px0 += M2, px1 -= M2
    {
        float m[2][4][4];
        #pragma unroll
        for (int mi = 0; mi < 2; mi++)
            #pragma unroll
            for (int ni = 0; ni < 4; ni++)
                #pragma unroll
                for (int j = 0; j < 4; j++) m[mi][ni][j] = 0.f;
        gemm_xi(m, a0 + 2u * V_XI_STRIDE, a1 + 2u * V_XI_STRIDE, Ub + 2 * 1536);
        #pragma unroll
        for (int mi = 0; mi < 2; mi++)
            #pragma unroll
            for (int ni = 0; ni < 4; ni++)
                #pragma unroll
                for (int j = 0; j < 4; j++) {
                    Y0[mi][ni][j] += m[mi][ni][j];
                    Y1[mi][ni][j] -= m[mi][ni][j];
                }
    }

    // ---- epilogue: STG.64 of adjacent output-px pairs (fully coalesced) ----
    const int xg = x0 + 2 * (lane >> 2);
    #pragma unroll
    for (int mi = 0; mi < 2; mi++)
        #pragma unroll
        for (int yr = 0; yr < 2; yr++) {
            const int y = y0 + 4 * wm + 2 * mi + yr;
            #pragma unroll
            for (int ni = 0; ni < 4; ni++)
                #pragma unroll
                for (int j = 0; j < 2; j++) {
                    const int o = wn * 32 + ni * 8 + 2 * (lane & 3) + j;
                    float2 v = make_float2(Y0[mi][ni][yr * 2 + j],
                                           Y1[mi][ni][yr * 2 + j]);
                    *reinterpret_cast<float2*>(
                        out + ((size_t)(b * 64 + o) << 18) + ((size_t)y << 9) + xg) = v;
                }
        }
}

// ---------------------------------------------------------------------------
// Harness entry point.
//   d_in[0] = input  (4, 64, 512, 512) float
//   d_in[1] = style  (4, 64)           float
//   d_in[2] = weight (64, 64, 3, 3)    float
//   d_out   = (4, 64, 512, 512) float
// ---------------------------------------------------------------------------
extern "C" void kernel_launch(void* const* d_in, const int* in_sizes, int n_in,
                              void* d_out, int out_size) {
    const float* input  = (const float*)d_in[0];
    const float* style  = (const float*)d_in[1];
    const float* weight = (const float*)d_in[2];
    float* out = (float*)d_out;

    cudaFuncSetAttribute(conv_kernel, cudaFuncAttributeMaxDynamicSharedMemorySize,
                         CONV_SMEM);

    modulate_kernel<<<256, 256>>>(weight, style);
    conv_kernel<<<dim3(32, 64, 4), 128, CONV_SMEM>>>(input, out);
}